// round 3
// baseline (speedup 1.0000x reference)
#include <cuda_runtime.h>
#include <math.h>
#include <stdint.h>

// Problem dims (fixed)
#define B_  4
#define S_  2048
#define E_  2048
#define H_  16
#define D_  128
#define F_  8192
#define NTOK (B_ * S_)          // 8192 tokens
#define QKV_STRIDE (3 * E_)     // 6144 per token in qkv buffer

// ---------------------------------------------------------------------------
// Scratch (device globals; allocation inside kernel_launch is forbidden)
// ---------------------------------------------------------------------------
__device__ float g_ln [(size_t)NTOK * E_];   //  64 MB : layernorm output (reused)
__device__ float g_qkv[(size_t)NTOK * QKV_STRIDE]; // 192 MB
__device__ float g_ctx[(size_t)NTOK * E_];   //  64 MB : attention context
__device__ float g_fc [(size_t)NTOK * F_];   // 256 MB : MLP hidden

// ---------------------------------------------------------------------------
// Block reduction helper (256 threads)
// ---------------------------------------------------------------------------
__device__ __forceinline__ float blk_reduce_sum(float v, float* sbuf) {
    int lane = threadIdx.x & 31, wid = threadIdx.x >> 5;
#pragma unroll
    for (int o = 16; o; o >>= 1) v += __shfl_xor_sync(0xffffffffu, v, o);
    if (lane == 0) sbuf[wid] = v;
    __syncthreads();
    if (threadIdx.x < 32) {
        float u = (threadIdx.x < 8) ? sbuf[threadIdx.x] : 0.f;
#pragma unroll
        for (int o = 4; o; o >>= 1) u += __shfl_xor_sync(0xffffffffu, u, o);
        if (threadIdx.x == 0) sbuf[0] = u;
    }
    __syncthreads();
    float r = sbuf[0];
    __syncthreads();
    return r;
}

// ---------------------------------------------------------------------------
// LayerNorm: one block per row of 2048, 256 threads, 8 elems/thread
// ---------------------------------------------------------------------------
__global__ __launch_bounds__(256) void ln_kernel(
    const float* __restrict__ x, const float* __restrict__ w,
    const float* __restrict__ b, float* __restrict__ out)
{
    __shared__ float sbuf[8];
    size_t base = (size_t)blockIdx.x * E_;
    int t = threadIdx.x;

    float4 v0 = *(const float4*)(x + base + 4 * t);
    float4 v1 = *(const float4*)(x + base + 4 * t + 1024);

    float s = v0.x + v0.y + v0.z + v0.w + v1.x + v1.y + v1.z + v1.w;
    float mean = blk_reduce_sum(s, sbuf) * (1.f / E_);

    float d, sq = 0.f;
    d = v0.x - mean; sq += d * d;  d = v0.y - mean; sq += d * d;
    d = v0.z - mean; sq += d * d;  d = v0.w - mean; sq += d * d;
    d = v1.x - mean; sq += d * d;  d = v1.y - mean; sq += d * d;
    d = v1.z - mean; sq += d * d;  d = v1.w - mean; sq += d * d;
    float var = blk_reduce_sum(sq, sbuf) * (1.f / E_);
    float r = rsqrtf(var + 1e-5f);

    float4 w0 = *(const float4*)(w + 4 * t);
    float4 w1 = *(const float4*)(w + 4 * t + 1024);
    float4 b0 = *(const float4*)(b + 4 * t);
    float4 b1 = *(const float4*)(b + 4 * t + 1024);

    float4 o0, o1;
    o0.x = (v0.x - mean) * r * w0.x + b0.x;
    o0.y = (v0.y - mean) * r * w0.y + b0.y;
    o0.z = (v0.z - mean) * r * w0.z + b0.z;
    o0.w = (v0.w - mean) * r * w0.w + b0.w;
    o1.x = (v1.x - mean) * r * w1.x + b1.x;
    o1.y = (v1.y - mean) * r * w1.y + b1.y;
    o1.z = (v1.z - mean) * r * w1.z + b1.z;
    o1.w = (v1.w - mean) * r * w1.w + b1.w;
    *(float4*)(out + base + 4 * t) = o0;
    *(float4*)(out + base + 4 * t + 1024) = o1;
}

// ---------------------------------------------------------------------------
// SGEMM: C[M,N] = A[M,K] @ B[K,N] + bias, optional GELU or residual add.
// 128x128x16 block tile, 256 threads, 8x8 per-thread with split fragments.
// All M,N divisible by 128; K divisible by 16 (true for every call here).
// ---------------------------------------------------------------------------
#define EPI_BIAS 0
#define EPI_GELU 1
#define EPI_RES  2

__device__ __forceinline__ float gelu_tanh(float x) {
    float x3 = x * x * x;
    float t = tanhf(0.7978845608028654f * (x + 0.044715f * x3));
    return 0.5f * x * (1.f + t);
}

template <int EPI>
__global__ __launch_bounds__(256) void sgemm_kernel(
    const float* __restrict__ A, const float* __restrict__ Bm,
    const float* __restrict__ bias, const float* __restrict__ res,
    float* __restrict__ C, int M, int N, int K)
{
    __shared__ float As[16][128];
    __shared__ float Bs[16][128];

    int tid = threadIdx.x;
    int bm = blockIdx.y * 128, bn = blockIdx.x * 128;
    int tx = tid & 15, ty = tid >> 4;

    float acc[8][8];
#pragma unroll
    for (int i = 0; i < 8; i++)
#pragma unroll
        for (int j = 0; j < 8; j++) acc[i][j] = 0.f;

    for (int k0 = 0; k0 < K; k0 += 16) {
        // Load A tile 128x16 (store transposed)
#pragma unroll
        for (int it = 0; it < 2; it++) {
            int idx = tid + it * 256;
            int r = idx >> 2, c4 = (idx & 3) * 4;
            float4 a = *(const float4*)&A[(size_t)(bm + r) * K + k0 + c4];
            As[c4 + 0][r] = a.x; As[c4 + 1][r] = a.y;
            As[c4 + 2][r] = a.z; As[c4 + 3][r] = a.w;
        }
        // Load B tile 16x128
#pragma unroll
        for (int it = 0; it < 2; it++) {
            int idx = tid + it * 256;
            int r = idx >> 5, c4 = (idx & 31) * 4;
            *(float4*)&Bs[r][c4] = *(const float4*)&Bm[(size_t)(k0 + r) * N + bn + c4];
        }
        __syncthreads();

#pragma unroll
        for (int kk = 0; kk < 16; kk++) {
            float4 a0 = *(const float4*)&As[kk][ty * 4];
            float4 a1 = *(const float4*)&As[kk][64 + ty * 4];
            float4 b0 = *(const float4*)&Bs[kk][tx * 4];
            float4 b1 = *(const float4*)&Bs[kk][64 + tx * 4];
            float af[8] = {a0.x, a0.y, a0.z, a0.w, a1.x, a1.y, a1.z, a1.w};
            float bf[8] = {b0.x, b0.y, b0.z, b0.w, b1.x, b1.y, b1.z, b1.w};
#pragma unroll
            for (int i = 0; i < 8; i++)
#pragma unroll
                for (int j = 0; j < 8; j++) acc[i][j] += af[i] * bf[j];
        }
        __syncthreads();
    }

    // Epilogue
    float4 bia0 = *(const float4*)&bias[bn + tx * 4];
    float4 bia1 = *(const float4*)&bias[bn + 64 + tx * 4];
    float bf0[4] = {bia0.x, bia0.y, bia0.z, bia0.w};
    float bf1[4] = {bia1.x, bia1.y, bia1.z, bia1.w};

#pragma unroll
    for (int i = 0; i < 8; i++) {
        int m = bm + ((i < 4) ? (ty * 4 + i) : (64 + ty * 4 + i - 4));
        size_t off0 = (size_t)m * N + bn + tx * 4;
        size_t off1 = (size_t)m * N + bn + 64 + tx * 4;
        float c0[4], c1[4];
#pragma unroll
        for (int j = 0; j < 4; j++) { c0[j] = acc[i][j] + bf0[j]; c1[j] = acc[i][j + 4] + bf1[j]; }
        if (EPI == EPI_GELU) {
#pragma unroll
            for (int j = 0; j < 4; j++) { c0[j] = gelu_tanh(c0[j]); c1[j] = gelu_tanh(c1[j]); }
        }
        if (EPI == EPI_RES) {
            float4 r0 = *(const float4*)&res[off0];
            float4 r1 = *(const float4*)&res[off1];
            c0[0] += r0.x; c0[1] += r0.y; c0[2] += r0.z; c0[3] += r0.w;
            c1[0] += r1.x; c1[1] += r1.y; c1[2] += r1.z; c1[3] += r1.w;
        }
        float4 s0 = {c0[0], c0[1], c0[2], c0[3]};
        float4 s1 = {c1[0], c1[1], c1[2], c1[3]};
        *(float4*)&C[off0] = s0;
        *(float4*)&C[off1] = s1;
    }
}

// ---------------------------------------------------------------------------
// Flash attention (fp32, causal). BM=BN=64, D=128, online softmax.
// grid = (S/64, H, B), 256 threads. Dynamic smem ~117 KB.
// ---------------------------------------------------------------------------
#define QKV_PAD 132   // 128 + 4 pad (row stride, floats)
#define SS_PAD  68    // 64 + 4 pad

// smem float offsets
#define OFF_Q 0
#define OFF_K (64 * QKV_PAD)
#define OFF_V (2 * 64 * QKV_PAD)
#define OFF_S (3 * 64 * QKV_PAD)
#define OFF_M (OFF_S + 64 * SS_PAD)
#define OFF_L (OFF_M + 64)
#define OFF_A (OFF_L + 64)
#define ATTN_SMEM_FLOATS (OFF_A + 64)
#define ATTN_SMEM_BYTES (ATTN_SMEM_FLOATS * 4)

__global__ __launch_bounds__(256, 1) void attn_kernel(
    const float* __restrict__ qkv, float* __restrict__ ctx)
{
    extern __shared__ float sm[];
    float* sQ = sm + OFF_Q;
    float* sK = sm + OFF_K;
    float* sV = sm + OFF_V;
    float* sS = sm + OFF_S;
    float* sMx = sm + OFF_M;
    float* sL  = sm + OFF_L;
    float* sAl = sm + OFF_A;

    int tid = threadIdx.x;
    int tx = tid & 15, ty = tid >> 4;
    int q0 = blockIdx.x * 64;
    int h = blockIdx.y;
    int b = blockIdx.z;

    const float scale = 0.08838834764831845f; // rsqrt(128)
    size_t tok_base = (size_t)(b * S_) * QKV_STRIDE + h * D_;

    // Load Q tile (64 x 128), pad stride 132
#pragma unroll
    for (int it = 0; it < 8; it++) {
        int idx = tid + it * 256;
        int r = idx >> 5, c4 = (idx & 31) * 4;
        float4 v = *(const float4*)&qkv[tok_base + (size_t)(q0 + r) * QKV_STRIDE + c4];
        *(float4*)&sQ[r * QKV_PAD + c4] = v;
    }
    if (tid < 64) { sMx[tid] = -INFINITY; sL[tid] = 0.f; }

    float o[4][8];
#pragma unroll
    for (int i = 0; i < 4; i++)
#pragma unroll
        for (int c = 0; c < 8; c++) o[i][c] = 0.f;

    __syncthreads();

    for (int k0 = 0; k0 <= q0; k0 += 64) {
        // Load K and V tiles
#pragma unroll
        for (int it = 0; it < 8; it++) {
            int idx = tid + it * 256;
            int r = idx >> 5, c4 = (idx & 31) * 4;
            size_t g = tok_base + (size_t)(k0 + r) * QKV_STRIDE + c4;
            *(float4*)&sK[r * QKV_PAD + c4] = *(const float4*)&qkv[g + E_];       // t=1
            *(float4*)&sV[r * QKV_PAD + c4] = *(const float4*)&qkv[g + 2 * E_];   // t=2
        }
        __syncthreads();

        // S = Q @ K^T (64x64), thread computes 4x4 with split-16 mapping
        float sacc[4][4];
#pragma unroll
        for (int i = 0; i < 4; i++)
#pragma unroll
            for (int j = 0; j < 4; j++) sacc[i][j] = 0.f;

#pragma unroll 4
        for (int d4 = 0; d4 < 32; d4++) {
            float4 qv[4], kv[4];
#pragma unroll
            for (int i = 0; i < 4; i++) qv[i] = *(const float4*)&sQ[(ty + i * 16) * QKV_PAD + d4 * 4];
#pragma unroll
            for (int j = 0; j < 4; j++) kv[j] = *(const float4*)&sK[(tx + j * 16) * QKV_PAD + d4 * 4];
#pragma unroll
            for (int i = 0; i < 4; i++)
#pragma unroll
                for (int j = 0; j < 4; j++) {
                    sacc[i][j] += qv[i].x * kv[j].x + qv[i].y * kv[j].y
                                + qv[i].z * kv[j].z + qv[i].w * kv[j].w;
                }
        }
        bool diag = (k0 == q0);
#pragma unroll
        for (int i = 0; i < 4; i++) {
            int qi = ty + i * 16;
#pragma unroll
            for (int j = 0; j < 4; j++) {
                int kj = tx + j * 16;
                float sv = sacc[i][j] * scale;
                if (diag && kj > qi) sv = -1e9f;
                sS[qi * SS_PAD + kj] = sv;
            }
        }
        __syncthreads();

        // Online softmax: warp w handles rows w*8 .. w*8+7
        {
            int w = tid >> 5, lane = tid & 31;
#pragma unroll
            for (int rr = 0; rr < 8; rr++) {
                int r = w * 8 + rr;
                float v0 = sS[r * SS_PAD + lane];
                float v1 = sS[r * SS_PAD + lane + 32];
                float mt = fmaxf(v0, v1);
#pragma unroll
                for (int off = 16; off; off >>= 1) mt = fmaxf(mt, __shfl_xor_sync(0xffffffffu, mt, off));
                float mo = sMx[r];
                float mn = fmaxf(mo, mt);
                float p0 = __expf(v0 - mn), p1 = __expf(v1 - mn);
                float su = p0 + p1;
#pragma unroll
                for (int off = 16; off; off >>= 1) su += __shfl_xor_sync(0xffffffffu, su, off);
                float al = __expf(mo - mn);
                if (lane == 0) { sL[r] = sL[r] * al + su; sMx[r] = mn; sAl[r] = al; }
                sS[r * SS_PAD + lane] = p0;
                sS[r * SS_PAD + lane + 32] = p1;
            }
        }
        __syncthreads();

        // O = O*alpha + P @ V
        float al[4];
#pragma unroll
        for (int i = 0; i < 4; i++) al[i] = sAl[ty + i * 16];
#pragma unroll
        for (int i = 0; i < 4; i++)
#pragma unroll
            for (int c = 0; c < 8; c++) o[i][c] *= al[i];

#pragma unroll 4
        for (int k = 0; k < 64; k++) {
            float p[4];
#pragma unroll
            for (int i = 0; i < 4; i++) p[i] = sS[(ty + i * 16) * SS_PAD + k];
            float4 v0 = *(const float4*)&sV[k * QKV_PAD + tx * 4];
            float4 v1 = *(const float4*)&sV[k * QKV_PAD + 64 + tx * 4];
#pragma unroll
            for (int i = 0; i < 4; i++) {
                o[i][0] += p[i] * v0.x; o[i][1] += p[i] * v0.y;
                o[i][2] += p[i] * v0.z; o[i][3] += p[i] * v0.w;
                o[i][4] += p[i] * v1.x; o[i][5] += p[i] * v1.y;
                o[i][6] += p[i] * v1.z; o[i][7] += p[i] * v1.w;
            }
        }
        __syncthreads();
    }

    // Normalize and write ctx[token][h*128 + d]
#pragma unroll
    for (int i = 0; i < 4; i++) {
        int r = ty + i * 16;
        float linv = 1.f / sL[r];
        size_t base = (size_t)(b * S_ + q0 + r) * E_ + h * D_;
        float4 w0 = {o[i][0] * linv, o[i][1] * linv, o[i][2] * linv, o[i][3] * linv};
        float4 w1 = {o[i][4] * linv, o[i][5] * linv, o[i][6] * linv, o[i][7] * linv};
        *(float4*)&ctx[base + tx * 4] = w0;
        *(float4*)&ctx[base + 64 + tx * 4] = w1;
    }
}

// ---------------------------------------------------------------------------
// Launch
// ---------------------------------------------------------------------------
extern "C" void kernel_launch(void* const* d_in, const int* in_sizes, int n_in,
                              void* d_out, int out_size)
{
    const float* x           = (const float*)d_in[0];
    const float* ln1_w       = (const float*)d_in[1];
    const float* ln1_b       = (const float*)d_in[2];
    const float* c_attn_w    = (const float*)d_in[3];   // [E, 3*H*D] row-major
    const float* c_attn_b    = (const float*)d_in[4];   // [3*H*D]
    const float* c_proj_w    = (const float*)d_in[5];   // [H*D, E]
    const float* c_proj_b    = (const float*)d_in[6];
    const float* ln2_w       = (const float*)d_in[7];
    const float* ln2_b       = (const float*)d_in[8];
    const float* c_fc_w      = (const float*)d_in[9];   // [E, F]
    const float* c_fc_b      = (const float*)d_in[10];
    const float* c_mlp_proj_w= (const float*)d_in[11];  // [F, E]
    const float* c_mlp_proj_b= (const float*)d_in[12];
    float* out = (float*)d_out;

    void *p_ln, *p_qkv, *p_ctx, *p_fc;
    cudaGetSymbolAddress(&p_ln,  g_ln);
    cudaGetSymbolAddress(&p_qkv, g_qkv);
    cudaGetSymbolAddress(&p_ctx, g_ctx);
    cudaGetSymbolAddress(&p_fc,  g_fc);
    float* ln  = (float*)p_ln;
    float* qkv = (float*)p_qkv;
    float* ctx = (float*)p_ctx;
    float* fc  = (float*)p_fc;

    cudaFuncSetAttribute(attn_kernel, cudaFuncAttributeMaxDynamicSharedMemorySize, ATTN_SMEM_BYTES);

    // 1. ln1(x) -> ln
    ln_kernel<<<NTOK, 256>>>(x, ln1_w, ln1_b, ln);

    // 2. qkv = ln @ c_attn_w + c_attn_b   [8192 x 6144]
    sgemm_kernel<EPI_BIAS><<<dim3(QKV_STRIDE / 128, NTOK / 128), 256>>>(
        ln, c_attn_w, c_attn_b, nullptr, qkv, NTOK, QKV_STRIDE, E_);

    // 3. attention -> ctx  [8192 x 2048]
    attn_kernel<<<dim3(S_ / 64, H_, B_), 256, ATTN_SMEM_BYTES>>>(qkv, ctx);

    // 4. x2 = ctx @ c_proj_w + c_proj_b + x  -> d_out
    sgemm_kernel<EPI_RES><<<dim3(E_ / 128, NTOK / 128), 256>>>(
        ctx, c_proj_w, c_proj_b, x, out, NTOK, E_, E_);

    // 5. ln2(x2) -> ln
    ln_kernel<<<NTOK, 256>>>(out, ln2_w, ln2_b, ln);

    // 6. fc = gelu(ln @ c_fc_w + c_fc_b)  [8192 x 8192]
    sgemm_kernel<EPI_GELU><<<dim3(F_ / 128, NTOK / 128), 256>>>(
        ln, c_fc_w, c_fc_b, nullptr, fc, NTOK, F_, E_);

    // 7. out = fc @ c_mlp_proj_w + c_mlp_proj_b + x2(d_out)  -> d_out
    sgemm_kernel<EPI_RES><<<dim3(E_ / 128, NTOK / 128), 256>>>(
        fc, c_mlp_proj_w, c_mlp_proj_b, out, out, NTOK, E_, F_);

    (void)in_sizes; (void)n_in; (void)out_size;
}

// round 8
// speedup vs baseline: 2.0431x; 2.0431x over previous
#include <cuda_runtime.h>
#include <cuda_bf16.h>
#include <math.h>
#include <stdint.h>

// Problem dims (fixed)
#define B_  4
#define S_  2048
#define E_  2048
#define H_  16
#define D_  128
#define F_  8192
#define NTOK (B_ * S_)
#define QKV_STRIDE (3 * E_)

// ---------------------------------------------------------------------------
// Scratch (device globals)
// ---------------------------------------------------------------------------
// Transposed+split weights, packed: qkv | proj | fc | mlp  (each [N,K] bf16)
#define WOFF_QKV 0u
#define WOFF_PROJ 12582912u               // 6144*2048
#define WOFF_FC   16777216u               // + 2048*2048
#define WOFF_MLP  33554432u               // + 2048*8192
#define WTOT      50331648u               // + 8192*2048
__device__ __nv_bfloat16 g_wt_hi[WTOT];
__device__ __nv_bfloat16 g_wt_lo[WTOT];
// Activation hi/lo planes [8192 x 2048] (reused: ln1 -> ctx -> ln2)
__device__ __nv_bfloat16 g_act_hi[(size_t)NTOK * E_];
__device__ __nv_bfloat16 g_act_lo[(size_t)NTOK * E_];
// MLP hidden hi/lo [8192 x 8192]
__device__ __nv_bfloat16 g_fc_hi[(size_t)NTOK * F_];
__device__ __nv_bfloat16 g_fc_lo[(size_t)NTOK * F_];
// QKV fp32 [8192 x 6144]
__device__ float g_qkv[(size_t)NTOK * QKV_STRIDE];

// ---------------------------------------------------------------------------
// PTX helpers (portable sm_80+ subset only — NO tcgen05 at compute_103)
// ---------------------------------------------------------------------------
__device__ __forceinline__ uint32_t smem_to_u32(const void* p) {
    uint32_t a;
    asm("{ .reg .u64 t; cvta.to.shared.u64 t, %1; cvt.u32.u64 %0, t; }" : "=r"(a) : "l"(p));
    return a;
}
__device__ __forceinline__ void cpa16(uint32_t dst, const void* src) {
    asm volatile("cp.async.cg.shared.global [%0], [%1], 16;" :: "r"(dst), "l"(src) : "memory");
}
#define CP_COMMIT() asm volatile("cp.async.commit_group;" ::: "memory")

__device__ __forceinline__ void ldsm4(uint32_t& r0, uint32_t& r1, uint32_t& r2, uint32_t& r3,
                                      uint32_t a) {
    asm volatile("ldmatrix.sync.aligned.m8n8.x4.shared.b16 {%0,%1,%2,%3}, [%4];"
                 : "=r"(r0), "=r"(r1), "=r"(r2), "=r"(r3) : "r"(a));
}
__device__ __forceinline__ void mma16816(float* c, const uint32_t* a, const uint32_t* b) {
    asm volatile(
        "mma.sync.aligned.m16n8k16.row.col.f32.bf16.bf16.f32 "
        "{%0,%1,%2,%3}, {%4,%5,%6,%7}, {%8,%9}, {%0,%1,%2,%3};"
        : "+f"(c[0]), "+f"(c[1]), "+f"(c[2]), "+f"(c[3])
        : "r"(a[0]), "r"(a[1]), "r"(a[2]), "r"(a[3]), "r"(b[0]), "r"(b[1]));
}

__device__ __forceinline__ void split2_store(float a, float b,
                                             __nv_bfloat16* hp, __nv_bfloat16* lp, size_t idx) {
    __nv_bfloat16 ha = __float2bfloat16(a);
    __nv_bfloat16 hb = __float2bfloat16(b);
    __nv_bfloat16 la = __float2bfloat16(a - __bfloat162float(ha));
    __nv_bfloat16 lb = __float2bfloat16(b - __bfloat162float(hb));
    __nv_bfloat162 h2; h2.x = ha; h2.y = hb;
    __nv_bfloat162 l2; l2.x = la; l2.y = lb;
    *(__nv_bfloat162*)(hp + idx) = h2;
    *(__nv_bfloat162*)(lp + idx) = l2;
}

// ---------------------------------------------------------------------------
// Weight prep: W[K,N] fp32 -> Th/Tl[N,K] bf16 (transpose + split)
// ---------------------------------------------------------------------------
__global__ __launch_bounds__(256) void wsplit_t_kernel(
    const float* __restrict__ W, __nv_bfloat16* __restrict__ Th,
    __nv_bfloat16* __restrict__ Tl, int K, int N)
{
    __shared__ float s[32][33];
    int n0 = blockIdx.x * 32, k0 = blockIdx.y * 32;
    int tx = threadIdx.x, ty = threadIdx.y;
#pragma unroll
    for (int j = 0; j < 4; j++)
        s[ty + j * 8][tx] = W[(size_t)(k0 + ty + j * 8) * N + n0 + tx];
    __syncthreads();
#pragma unroll
    for (int j = 0; j < 4; j++) {
        float v = s[tx][ty + j * 8];
        __nv_bfloat16 h = __float2bfloat16(v);
        __nv_bfloat16 l = __float2bfloat16(v - __bfloat162float(h));
        size_t o = (size_t)(n0 + ty + j * 8) * K + k0 + tx;
        Th[o] = h; Tl[o] = l;
    }
}

// ---------------------------------------------------------------------------
// Block reduction (256 threads)
// ---------------------------------------------------------------------------
__device__ __forceinline__ float blk_reduce_sum(float v, float* sbuf) {
    int lane = threadIdx.x & 31, wid = threadIdx.x >> 5;
#pragma unroll
    for (int o = 16; o; o >>= 1) v += __shfl_xor_sync(0xffffffffu, v, o);
    if (lane == 0) sbuf[wid] = v;
    __syncthreads();
    if (threadIdx.x < 32) {
        float u = (threadIdx.x < 8) ? sbuf[threadIdx.x] : 0.f;
#pragma unroll
        for (int o = 4; o; o >>= 1) u += __shfl_xor_sync(0xffffffffu, u, o);
        if (threadIdx.x == 0) sbuf[0] = u;
    }
    __syncthreads();
    float r = sbuf[0];
    __syncthreads();
    return r;
}

// ---------------------------------------------------------------------------
// LayerNorm -> bf16 hi/lo planes
// ---------------------------------------------------------------------------
__global__ __launch_bounds__(256) void ln_kernel(
    const float* __restrict__ x, const float* __restrict__ w,
    const float* __restrict__ b, __nv_bfloat16* __restrict__ oh,
    __nv_bfloat16* __restrict__ ol)
{
    __shared__ float sbuf[8];
    size_t base = (size_t)blockIdx.x * E_;
    int t = threadIdx.x;

    float4 v0 = *(const float4*)(x + base + 4 * t);
    float4 v1 = *(const float4*)(x + base + 4 * t + 1024);
    float s = v0.x + v0.y + v0.z + v0.w + v1.x + v1.y + v1.z + v1.w;
    float mean = blk_reduce_sum(s, sbuf) * (1.f / E_);
    float d, sq = 0.f;
    d = v0.x - mean; sq += d * d;  d = v0.y - mean; sq += d * d;
    d = v0.z - mean; sq += d * d;  d = v0.w - mean; sq += d * d;
    d = v1.x - mean; sq += d * d;  d = v1.y - mean; sq += d * d;
    d = v1.z - mean; sq += d * d;  d = v1.w - mean; sq += d * d;
    float var = blk_reduce_sum(sq, sbuf) * (1.f / E_);
    float r = rsqrtf(var + 1e-5f);

    float4 w0 = *(const float4*)(w + 4 * t);
    float4 w1 = *(const float4*)(w + 4 * t + 1024);
    float4 b0 = *(const float4*)(b + 4 * t);
    float4 b1 = *(const float4*)(b + 4 * t + 1024);

    float o0x = (v0.x - mean) * r * w0.x + b0.x;
    float o0y = (v0.y - mean) * r * w0.y + b0.y;
    float o0z = (v0.z - mean) * r * w0.z + b0.z;
    float o0w = (v0.w - mean) * r * w0.w + b0.w;
    float o1x = (v1.x - mean) * r * w1.x + b1.x;
    float o1y = (v1.y - mean) * r * w1.y + b1.y;
    float o1z = (v1.z - mean) * r * w1.z + b1.z;
    float o1w = (v1.w - mean) * r * w1.w + b1.w;

    split2_store(o0x, o0y, oh, ol, base + 4 * t);
    split2_store(o0z, o0w, oh, ol, base + 4 * t + 2);
    split2_store(o1x, o1y, oh, ol, base + 4 * t + 1024);
    split2_store(o1z, o1w, oh, ol, base + 4 * t + 1026);
}

// ---------------------------------------------------------------------------
// HMMA GEMM: C[M,N] = (Ah+Al)[M,K] @ (Bh+Bl)[N,K]^T   (3-term bf16 split)
// mma.sync.m16n8k16 + ldmatrix + cp.async, CTA 128x128, BK=32, 3 stages.
// 8 warps in 2(m) x 4(n); warp tile 64x32.
// ---------------------------------------------------------------------------
#define EPI_QKV  0   // fp32 out = acc + bias
#define EPI_GELU 1   // bf16 hi/lo out = split(gelu(acc + bias))
#define EPI_RES  2   // fp32 out = acc + bias + res

#define BM 128
#define BN 128
#define BK 32
// smem rows padded to 80B (40 bf16): row*80 mod 128 covers 8 distinct 16B banks
#define ROWB 80
#define SA_H 0
#define SA_L 10240
#define SB_H 20480
#define SB_L 30720
#define STAGE_BYTES 40960
#define HMMA_SMEM (3 * STAGE_BYTES)

__device__ __forceinline__ float gelu_tanh(float x) {
    float x3 = x * x * x;
    float t = tanhf(0.7978845608028654f * (x + 0.044715f * x3));
    return 0.5f * x * (1.f + t);
}

__device__ __forceinline__ void g2s_stage(
    uint32_t sb, const __nv_bfloat16* __restrict__ Ah, const __nv_bfloat16* __restrict__ Al,
    const __nv_bfloat16* __restrict__ Bh, const __nv_bfloat16* __restrict__ Bl,
    int bm, int bn, int K, int k0, int tid)
{
    // 128 rows x 32 bf16 (64B) per plane = 512 x 16B chunks; 256 threads x 2 iters
#pragma unroll
    for (int it = 0; it < 2; it++) {
        int c = tid + it * 256;
        int row = c >> 2, ch = c & 3;
        uint32_t off = (uint32_t)row * ROWB + ch * 16;
        size_t ga = (size_t)(bm + row) * K + k0 + ch * 8;
        size_t gb = (size_t)(bn + row) * K + k0 + ch * 8;
        cpa16(sb + SA_H + off, Ah + ga);
        cpa16(sb + SA_L + off, Al + ga);
        cpa16(sb + SB_H + off, Bh + gb);
        cpa16(sb + SB_L + off, Bl + gb);
    }
    CP_COMMIT();
}

template <int EPI>
__global__ __launch_bounds__(256, 1) void hmma_kernel(
    const __nv_bfloat16* __restrict__ Ah, const __nv_bfloat16* __restrict__ Al,
    const __nv_bfloat16* __restrict__ Bh, const __nv_bfloat16* __restrict__ Bl,
    const float* __restrict__ bias, const float* __restrict__ res,
    float* __restrict__ Cf, __nv_bfloat16* __restrict__ Chi,
    __nv_bfloat16* __restrict__ Clo, int M, int N, int K)
{
    extern __shared__ char smem[];
    uint32_t sb0 = smem_to_u32(smem);
    int tid = threadIdx.x;
    int wid = tid >> 5, lane = tid & 31;
    int wm = (wid & 1) * 64, wn = (wid >> 1) * 32;
    int bm = blockIdx.y * BM, bn = blockIdx.x * BN;

    float acc[4][4][4];
#pragma unroll
    for (int i = 0; i < 4; i++)
#pragma unroll
        for (int j = 0; j < 4; j++)
#pragma unroll
            for (int k = 0; k < 4; k++) acc[i][j][k] = 0.f;

    // per-lane ldmatrix address components (byte offsets)
    uint32_t a_off = (uint32_t)(wm + (lane & 15)) * ROWB + ((lane >> 4) * 16);
    uint32_t b_off = (uint32_t)(wn + (lane & 7) + ((lane >> 4) * 8)) * ROWB
                   + (((lane >> 3) & 1) * 16);

    g2s_stage(sb0,                   Ah, Al, Bh, Bl, bm, bn, K, 0,  tid);
    g2s_stage(sb0 + STAGE_BYTES,     Ah, Al, Bh, Bl, bm, bn, K, BK, tid);

    int nk = K / BK;
    for (int kt = 0; kt < nk; kt++) {
        asm volatile("cp.async.wait_group 1;" ::: "memory");
        __syncthreads();
        // prefetch stage kt+2 into slot (kt+2)%3 (its consumers finished last iter)
        if (kt + 2 < nk)
            g2s_stage(sb0 + (uint32_t)((kt + 2) % 3) * STAGE_BYTES,
                      Ah, Al, Bh, Bl, bm, bn, K, (kt + 2) * BK, tid);
        else
            CP_COMMIT();

        uint32_t st = sb0 + (uint32_t)(kt % 3) * STAGE_BYTES;
#pragma unroll
        for (int ks = 0; ks < 2; ks++) {
            uint32_t koff = (uint32_t)ks * 32;   // 16 bf16 = 32 bytes
            uint32_t ah[4][4], al[4][4];
#pragma unroll
            for (int mi = 0; mi < 4; mi++) {
                uint32_t ra = st + SA_H + a_off + (uint32_t)mi * (16 * ROWB) + koff;
                ldsm4(ah[mi][0], ah[mi][1], ah[mi][2], ah[mi][3], ra);
                ldsm4(al[mi][0], al[mi][1], al[mi][2], al[mi][3], ra + (SA_L - SA_H));
            }
            uint32_t bh[2][4], bl[2][4];
#pragma unroll
            for (int ng = 0; ng < 2; ng++) {
                uint32_t rb = st + SB_H + b_off + (uint32_t)ng * (16 * ROWB) + koff;
                ldsm4(bh[ng][0], bh[ng][1], bh[ng][2], bh[ng][3], rb);
                ldsm4(bl[ng][0], bl[ng][1], bl[ng][2], bl[ng][3], rb + (SB_L - SB_H));
            }
#pragma unroll
            for (int mi = 0; mi < 4; mi++)
#pragma unroll
                for (int nf = 0; nf < 4; nf++) {
                    const uint32_t* B0 = &bh[nf >> 1][(nf & 1) * 2];
                    const uint32_t* B1 = &bl[nf >> 1][(nf & 1) * 2];
                    mma16816(acc[mi][nf], ah[mi], B0);
                    mma16816(acc[mi][nf], ah[mi], B1);
                    mma16816(acc[mi][nf], al[mi], B0);
                }
        }
    }

    // Epilogue: c0/c1 -> (m0, n0..n0+1); c2/c3 -> (m0+8, n0..n0+1)
    int mrow = bm + wm + (lane >> 2);
    int ncol0 = (lane & 3) * 2;
#pragma unroll
    for (int mi = 0; mi < 4; mi++) {
        int m0 = mrow + mi * 16;
#pragma unroll
        for (int nf = 0; nf < 4; nf++) {
            int n0 = bn + wn + nf * 8 + ncol0;
            float b0 = bias[n0], b1 = bias[n0 + 1];
            float v00 = acc[mi][nf][0] + b0, v01 = acc[mi][nf][1] + b1;
            float v10 = acc[mi][nf][2] + b0, v11 = acc[mi][nf][3] + b1;
            size_t o0 = (size_t)m0 * N + n0;
            size_t o1 = (size_t)(m0 + 8) * N + n0;
            if (EPI == EPI_GELU) {
                split2_store(gelu_tanh(v00), gelu_tanh(v01), Chi, Clo, o0);
                split2_store(gelu_tanh(v10), gelu_tanh(v11), Chi, Clo, o1);
            } else {
                if (EPI == EPI_RES) {
                    float2 r0 = *(const float2*)(res + o0);
                    float2 r1 = *(const float2*)(res + o1);
                    v00 += r0.x; v01 += r0.y; v10 += r1.x; v11 += r1.y;
                }
                float2 s0 = {v00, v01}, s1 = {v10, v11};
                *(float2*)(Cf + o0) = s0;
                *(float2*)(Cf + o1) = s1;
            }
        }
    }
}

// ---------------------------------------------------------------------------
// Flash attention (fp32, causal). BM=BN=64, D=128. Writes bf16 hi/lo ctx.
// ---------------------------------------------------------------------------
#define QKV_PAD 132
#define SS_PAD  68
#define OFF_Q 0
#define OFF_K (64 * QKV_PAD)
#define OFF_V (2 * 64 * QKV_PAD)
#define OFF_S (3 * 64 * QKV_PAD)
#define OFF_M (OFF_S + 64 * SS_PAD)
#define OFF_L (OFF_M + 64)
#define OFF_A (OFF_L + 64)
#define ATTN_SMEM_FLOATS (OFF_A + 64)
#define ATTN_SMEM_BYTES (ATTN_SMEM_FLOATS * 4)

__global__ __launch_bounds__(256, 1) void attn_kernel(
    const float* __restrict__ qkv, __nv_bfloat16* __restrict__ ctx_hi,
    __nv_bfloat16* __restrict__ ctx_lo)
{
    extern __shared__ float sm[];
    float* sQ = sm + OFF_Q;
    float* sK = sm + OFF_K;
    float* sV = sm + OFF_V;
    float* sS = sm + OFF_S;
    float* sMx = sm + OFF_M;
    float* sL  = sm + OFF_L;
    float* sAl = sm + OFF_A;

    int tid = threadIdx.x;
    int tx = tid & 15, ty = tid >> 4;
    int q0 = blockIdx.x * 64;
    int h = blockIdx.y;
    int b = blockIdx.z;

    const float scale = 0.08838834764831845f;
    size_t tok_base = (size_t)(b * S_) * QKV_STRIDE + h * D_;

#pragma unroll
    for (int it = 0; it < 8; it++) {
        int idx = tid + it * 256;
        int r = idx >> 5, c4 = (idx & 31) * 4;
        float4 v = *(const float4*)&qkv[tok_base + (size_t)(q0 + r) * QKV_STRIDE + c4];
        *(float4*)&sQ[r * QKV_PAD + c4] = v;
    }
    if (tid < 64) { sMx[tid] = -INFINITY; sL[tid] = 0.f; }

    float o[4][8];
#pragma unroll
    for (int i = 0; i < 4; i++)
#pragma unroll
        for (int c = 0; c < 8; c++) o[i][c] = 0.f;
    __syncthreads();

    for (int k0 = 0; k0 <= q0; k0 += 64) {
#pragma unroll
        for (int it = 0; it < 8; it++) {
            int idx = tid + it * 256;
            int r = idx >> 5, c4 = (idx & 31) * 4;
            size_t g = tok_base + (size_t)(k0 + r) * QKV_STRIDE + c4;
            *(float4*)&sK[r * QKV_PAD + c4] = *(const float4*)&qkv[g + E_];
            *(float4*)&sV[r * QKV_PAD + c4] = *(const float4*)&qkv[g + 2 * E_];
        }
        __syncthreads();

        float sacc[4][4];
#pragma unroll
        for (int i = 0; i < 4; i++)
#pragma unroll
            for (int j = 0; j < 4; j++) sacc[i][j] = 0.f;

#pragma unroll 4
        for (int d4 = 0; d4 < 32; d4++) {
            float4 qv[4], kv[4];
#pragma unroll
            for (int i = 0; i < 4; i++) qv[i] = *(const float4*)&sQ[(ty + i * 16) * QKV_PAD + d4 * 4];
#pragma unroll
            for (int j = 0; j < 4; j++) kv[j] = *(const float4*)&sK[(tx + j * 16) * QKV_PAD + d4 * 4];
#pragma unroll
            for (int i = 0; i < 4; i++)
#pragma unroll
                for (int j = 0; j < 4; j++)
                    sacc[i][j] += qv[i].x * kv[j].x + qv[i].y * kv[j].y
                                + qv[i].z * kv[j].z + qv[i].w * kv[j].w;
        }
        bool diag = (k0 == q0);
#pragma unroll
        for (int i = 0; i < 4; i++) {
            int qi = ty + i * 16;
#pragma unroll
            for (int j = 0; j < 4; j++) {
                int kj = tx + j * 16;
                float sv = sacc[i][j] * scale;
                if (diag && kj > qi) sv = -1e9f;
                sS[qi * SS_PAD + kj] = sv;
            }
        }
        __syncthreads();

        {
            int w = tid >> 5, lane = tid & 31;
#pragma unroll
            for (int rr = 0; rr < 8; rr++) {
                int r = w * 8 + rr;
                float v0 = sS[r * SS_PAD + lane];
                float v1 = sS[r * SS_PAD + lane + 32];
                float mt = fmaxf(v0, v1);
#pragma unroll
                for (int off = 16; off; off >>= 1) mt = fmaxf(mt, __shfl_xor_sync(0xffffffffu, mt, off));
                float mo = sMx[r];
                float mn = fmaxf(mo, mt);
                float p0 = __expf(v0 - mn), p1 = __expf(v1 - mn);
                float su = p0 + p1;
#pragma unroll
                for (int off = 16; off; off >>= 1) su += __shfl_xor_sync(0xffffffffu, su, off);
                float al = __expf(mo - mn);
                if (lane == 0) { sL[r] = sL[r] * al + su; sMx[r] = mn; sAl[r] = al; }
                sS[r * SS_PAD + lane] = p0;
                sS[r * SS_PAD + lane + 32] = p1;
            }
        }
        __syncthreads();

        float al[4];
#pragma unroll
        for (int i = 0; i < 4; i++) al[i] = sAl[ty + i * 16];
#pragma unroll
        for (int i = 0; i < 4; i++)
#pragma unroll
            for (int c = 0; c < 8; c++) o[i][c] *= al[i];

#pragma unroll 4
        for (int k = 0; k < 64; k++) {
            float p[4];
#pragma unroll
            for (int i = 0; i < 4; i++) p[i] = sS[(ty + i * 16) * SS_PAD + k];
            float4 v0 = *(const float4*)&sV[k * QKV_PAD + tx * 4];
            float4 v1 = *(const float4*)&sV[k * QKV_PAD + 64 + tx * 4];
#pragma unroll
            for (int i = 0; i < 4; i++) {
                o[i][0] += p[i] * v0.x; o[i][1] += p[i] * v0.y;
                o[i][2] += p[i] * v0.z; o[i][3] += p[i] * v0.w;
                o[i][4] += p[i] * v1.x; o[i][5] += p[i] * v1.y;
                o[i][6] += p[i] * v1.z; o[i][7] += p[i] * v1.w;
            }
        }
        __syncthreads();
    }

#pragma unroll
    for (int i = 0; i < 4; i++) {
        int r = ty + i * 16;
        float linv = 1.f / sL[r];
        size_t base = (size_t)(b * S_ + q0 + r) * E_ + h * D_;
        split2_store(o[i][0] * linv, o[i][1] * linv, ctx_hi, ctx_lo, base + tx * 4);
        split2_store(o[i][2] * linv, o[i][3] * linv, ctx_hi, ctx_lo, base + tx * 4 + 2);
        split2_store(o[i][4] * linv, o[i][5] * linv, ctx_hi, ctx_lo, base + 64 + tx * 4);
        split2_store(o[i][6] * linv, o[i][7] * linv, ctx_hi, ctx_lo, base + 64 + tx * 4 + 2);
    }
}

// ---------------------------------------------------------------------------
// Launch
// ---------------------------------------------------------------------------
extern "C" void kernel_launch(void* const* d_in, const int* in_sizes, int n_in,
                              void* d_out, int out_size)
{
    const float* x            = (const float*)d_in[0];
    const float* ln1_w        = (const float*)d_in[1];
    const float* ln1_b        = (const float*)d_in[2];
    const float* c_attn_w     = (const float*)d_in[3];
    const float* c_attn_b     = (const float*)d_in[4];
    const float* c_proj_w     = (const float*)d_in[5];
    const float* c_proj_b     = (const float*)d_in[6];
    const float* ln2_w        = (const float*)d_in[7];
    const float* ln2_b        = (const float*)d_in[8];
    const float* c_fc_w       = (const float*)d_in[9];
    const float* c_fc_b       = (const float*)d_in[10];
    const float* c_mlp_proj_w = (const float*)d_in[11];
    const float* c_mlp_proj_b = (const float*)d_in[12];
    float* out = (float*)d_out;

    void *p_wh, *p_wl, *p_ah, *p_al, *p_fh, *p_fl, *p_qkv;
    cudaGetSymbolAddress(&p_wh, g_wt_hi);
    cudaGetSymbolAddress(&p_wl, g_wt_lo);
    cudaGetSymbolAddress(&p_ah, g_act_hi);
    cudaGetSymbolAddress(&p_al, g_act_lo);
    cudaGetSymbolAddress(&p_fh, g_fc_hi);
    cudaGetSymbolAddress(&p_fl, g_fc_lo);
    cudaGetSymbolAddress(&p_qkv, g_qkv);
    __nv_bfloat16* wh = (__nv_bfloat16*)p_wh;
    __nv_bfloat16* wl = (__nv_bfloat16*)p_wl;
    __nv_bfloat16* ah = (__nv_bfloat16*)p_ah;
    __nv_bfloat16* al = (__nv_bfloat16*)p_al;
    __nv_bfloat16* fh = (__nv_bfloat16*)p_fh;
    __nv_bfloat16* fl = (__nv_bfloat16*)p_fl;
    float* qkv = (float*)p_qkv;

    cudaFuncSetAttribute(attn_kernel, cudaFuncAttributeMaxDynamicSharedMemorySize, ATTN_SMEM_BYTES);
    cudaFuncSetAttribute(hmma_kernel<EPI_QKV>,  cudaFuncAttributeMaxDynamicSharedMemorySize, HMMA_SMEM);
    cudaFuncSetAttribute(hmma_kernel<EPI_GELU>, cudaFuncAttributeMaxDynamicSharedMemorySize, HMMA_SMEM);
    cudaFuncSetAttribute(hmma_kernel<EPI_RES>,  cudaFuncAttributeMaxDynamicSharedMemorySize, HMMA_SMEM);

    dim3 tb(32, 8);
    // Weight prep: transpose + bf16 split
    wsplit_t_kernel<<<dim3(6144 / 32, 2048 / 32), tb>>>(c_attn_w,     wh + WOFF_QKV,  wl + WOFF_QKV,  2048, 6144);
    wsplit_t_kernel<<<dim3(2048 / 32, 2048 / 32), tb>>>(c_proj_w,     wh + WOFF_PROJ, wl + WOFF_PROJ, 2048, 2048);
    wsplit_t_kernel<<<dim3(8192 / 32, 2048 / 32), tb>>>(c_fc_w,       wh + WOFF_FC,   wl + WOFF_FC,   2048, 8192);
    wsplit_t_kernel<<<dim3(2048 / 32, 8192 / 32), tb>>>(c_mlp_proj_w, wh + WOFF_MLP,  wl + WOFF_MLP,  8192, 2048);

    // 1. ln1(x) -> act planes
    ln_kernel<<<NTOK, 256>>>(x, ln1_w, ln1_b, ah, al);

    // 2. qkv = ln1 @ Wqkv + b  (fp32)
    hmma_kernel<EPI_QKV><<<dim3(QKV_STRIDE / BN, NTOK / BM), 256, HMMA_SMEM>>>(
        ah, al, wh + WOFF_QKV, wl + WOFF_QKV, c_attn_b, nullptr,
        qkv, nullptr, nullptr, NTOK, QKV_STRIDE, E_);

    // 3. attention -> ctx planes (reuse act planes)
    attn_kernel<<<dim3(S_ / 64, H_, B_), 256, ATTN_SMEM_BYTES>>>(qkv, ah, al);

    // 4. x2 = ctx @ Wproj + b + x -> d_out (fp32)
    hmma_kernel<EPI_RES><<<dim3(E_ / BN, NTOK / BM), 256, HMMA_SMEM>>>(
        ah, al, wh + WOFF_PROJ, wl + WOFF_PROJ, c_proj_b, x,
        out, nullptr, nullptr, NTOK, E_, E_);

    // 5. ln2(x2) -> act planes
    ln_kernel<<<NTOK, 256>>>(out, ln2_w, ln2_b, ah, al);

    // 6. fc = gelu(ln2 @ Wfc + b) -> fc planes (bf16 hi/lo)
    hmma_kernel<EPI_GELU><<<dim3(F_ / BN, NTOK / BM), 256, HMMA_SMEM>>>(
        ah, al, wh + WOFF_FC, wl + WOFF_FC, c_fc_b, nullptr,
        nullptr, fh, fl, NTOK, F_, E_);

    // 7. out = fc @ Wmlp + b + x2 -> d_out (fp32, in-place residual)
    hmma_kernel<EPI_RES><<<dim3(E_ / BN, NTOK / BM), 256, HMMA_SMEM>>>(
        fh, fl, wh + WOFF_MLP, wl + WOFF_MLP, c_mlp_proj_b, out,
        out, nullptr, nullptr, NTOK, E_, F_);

    (void)in_sizes; (void)n_in; (void)out_size;
}

// round 9
// speedup vs baseline: 2.5088x; 1.2280x over previous
#include <cuda_runtime.h>
#include <cuda_bf16.h>
#include <math.h>
#include <stdint.h>

// Problem dims (fixed)
#define B_  4
#define S_  2048
#define E_  2048
#define H_  16
#define D_  128
#define F_  8192
#define NTOK (B_ * S_)
#define QKV_STRIDE (3 * E_)

// ---------------------------------------------------------------------------
// Scratch (device globals)
// ---------------------------------------------------------------------------
#define WOFF_QKV 0u
#define WOFF_PROJ 12582912u               // 6144*2048
#define WOFF_FC   16777216u               // + 2048*2048
#define WOFF_MLP  33554432u               // + 2048*8192
#define WTOT      50331648u               // + 8192*2048
__device__ __nv_bfloat16 g_wt_hi[WTOT];
__device__ __nv_bfloat16 g_wt_lo[WTOT];
// Activation hi/lo planes [8192 x 2048] (ln1 -> ctx -> ln2)
__device__ __nv_bfloat16 g_act_hi[(size_t)NTOK * E_];
__device__ __nv_bfloat16 g_act_lo[(size_t)NTOK * E_];
// Large planes [8192 x 8192]; also alias qkv planes [8192 x 6144]
__device__ __nv_bfloat16 g_fc_hi[(size_t)NTOK * F_];
__device__ __nv_bfloat16 g_fc_lo[(size_t)NTOK * F_];

// ---------------------------------------------------------------------------
// PTX helpers (portable sm_80+ subset only)
// ---------------------------------------------------------------------------
__device__ __forceinline__ uint32_t smem_to_u32(const void* p) {
    uint32_t a;
    asm("{ .reg .u64 t; cvta.to.shared.u64 t, %1; cvt.u32.u64 %0, t; }" : "=r"(a) : "l"(p));
    return a;
}
__device__ __forceinline__ void cpa16(uint32_t dst, const void* src) {
    asm volatile("cp.async.cg.shared.global [%0], [%1], 16;" :: "r"(dst), "l"(src) : "memory");
}
#define CP_COMMIT() asm volatile("cp.async.commit_group;" ::: "memory")

__device__ __forceinline__ void ldsm4(uint32_t& r0, uint32_t& r1, uint32_t& r2, uint32_t& r3,
                                      uint32_t a) {
    asm volatile("ldmatrix.sync.aligned.m8n8.x4.shared.b16 {%0,%1,%2,%3}, [%4];"
                 : "=r"(r0), "=r"(r1), "=r"(r2), "=r"(r3) : "r"(a));
}
__device__ __forceinline__ void ldsm4t(uint32_t& r0, uint32_t& r1, uint32_t& r2, uint32_t& r3,
                                       uint32_t a) {
    asm volatile("ldmatrix.sync.aligned.m8n8.x4.trans.shared.b16 {%0,%1,%2,%3}, [%4];"
                 : "=r"(r0), "=r"(r1), "=r"(r2), "=r"(r3) : "r"(a));
}
__device__ __forceinline__ void mma16816(float* c, const uint32_t* a, const uint32_t* b) {
    asm volatile(
        "mma.sync.aligned.m16n8k16.row.col.f32.bf16.bf16.f32 "
        "{%0,%1,%2,%3}, {%4,%5,%6,%7}, {%8,%9}, {%0,%1,%2,%3};"
        : "+f"(c[0]), "+f"(c[1]), "+f"(c[2]), "+f"(c[3])
        : "r"(a[0]), "r"(a[1]), "r"(a[2]), "r"(a[3]), "r"(b[0]), "r"(b[1]));
}

__device__ __forceinline__ void split2_store(float a, float b,
                                             __nv_bfloat16* hp, __nv_bfloat16* lp, size_t idx) {
    __nv_bfloat16 ha = __float2bfloat16(a);
    __nv_bfloat16 hb = __float2bfloat16(b);
    __nv_bfloat16 la = __float2bfloat16(a - __bfloat162float(ha));
    __nv_bfloat16 lb = __float2bfloat16(b - __bfloat162float(hb));
    __nv_bfloat162 h2; h2.x = ha; h2.y = hb;
    __nv_bfloat162 l2; l2.x = la; l2.y = lb;
    *(__nv_bfloat162*)(hp + idx) = h2;
    *(__nv_bfloat162*)(lp + idx) = l2;
}
// split two floats into packed bf16x2 hi and lo registers (low half = first arg)
__device__ __forceinline__ void splitpack(float a, float b, uint32_t& hi, uint32_t& lo) {
    __nv_bfloat16 ha = __float2bfloat16(a);
    __nv_bfloat16 hb = __float2bfloat16(b);
    __nv_bfloat16 la = __float2bfloat16(a - __bfloat162float(ha));
    __nv_bfloat16 lb = __float2bfloat16(b - __bfloat162float(hb));
    hi = (uint32_t)__bfloat16_as_ushort(ha) | ((uint32_t)__bfloat16_as_ushort(hb) << 16);
    lo = (uint32_t)__bfloat16_as_ushort(la) | ((uint32_t)__bfloat16_as_ushort(lb) << 16);
}

// ---------------------------------------------------------------------------
// Weight prep: W[K,N] fp32 -> Th/Tl[N,K] bf16 (transpose + split)
// ---------------------------------------------------------------------------
__global__ __launch_bounds__(256) void wsplit_t_kernel(
    const float* __restrict__ W, __nv_bfloat16* __restrict__ Th,
    __nv_bfloat16* __restrict__ Tl, int K, int N)
{
    __shared__ float s[32][33];
    int n0 = blockIdx.x * 32, k0 = blockIdx.y * 32;
    int tx = threadIdx.x, ty = threadIdx.y;
#pragma unroll
    for (int j = 0; j < 4; j++)
        s[ty + j * 8][tx] = W[(size_t)(k0 + ty + j * 8) * N + n0 + tx];
    __syncthreads();
#pragma unroll
    for (int j = 0; j < 4; j++) {
        float v = s[tx][ty + j * 8];
        __nv_bfloat16 h = __float2bfloat16(v);
        __nv_bfloat16 l = __float2bfloat16(v - __bfloat162float(h));
        size_t o = (size_t)(n0 + ty + j * 8) * K + k0 + tx;
        Th[o] = h; Tl[o] = l;
    }
}

// ---------------------------------------------------------------------------
// Block reduction (256 threads)
// ---------------------------------------------------------------------------
__device__ __forceinline__ float blk_reduce_sum(float v, float* sbuf) {
    int lane = threadIdx.x & 31, wid = threadIdx.x >> 5;
#pragma unroll
    for (int o = 16; o; o >>= 1) v += __shfl_xor_sync(0xffffffffu, v, o);
    if (lane == 0) sbuf[wid] = v;
    __syncthreads();
    if (threadIdx.x < 32) {
        float u = (threadIdx.x < 8) ? sbuf[threadIdx.x] : 0.f;
#pragma unroll
        for (int o = 4; o; o >>= 1) u += __shfl_xor_sync(0xffffffffu, u, o);
        if (threadIdx.x == 0) sbuf[0] = u;
    }
    __syncthreads();
    float r = sbuf[0];
    __syncthreads();
    return r;
}

// ---------------------------------------------------------------------------
// LayerNorm -> bf16 hi/lo planes
// ---------------------------------------------------------------------------
__global__ __launch_bounds__(256) void ln_kernel(
    const float* __restrict__ x, const float* __restrict__ w,
    const float* __restrict__ b, __nv_bfloat16* __restrict__ oh,
    __nv_bfloat16* __restrict__ ol)
{
    __shared__ float sbuf[8];
    size_t base = (size_t)blockIdx.x * E_;
    int t = threadIdx.x;

    float4 v0 = *(const float4*)(x + base + 4 * t);
    float4 v1 = *(const float4*)(x + base + 4 * t + 1024);
    float s = v0.x + v0.y + v0.z + v0.w + v1.x + v1.y + v1.z + v1.w;
    float mean = blk_reduce_sum(s, sbuf) * (1.f / E_);
    float d, sq = 0.f;
    d = v0.x - mean; sq += d * d;  d = v0.y - mean; sq += d * d;
    d = v0.z - mean; sq += d * d;  d = v0.w - mean; sq += d * d;
    d = v1.x - mean; sq += d * d;  d = v1.y - mean; sq += d * d;
    d = v1.z - mean; sq += d * d;  d = v1.w - mean; sq += d * d;
    float var = blk_reduce_sum(sq, sbuf) * (1.f / E_);
    float r = rsqrtf(var + 1e-5f);

    float4 w0 = *(const float4*)(w + 4 * t);
    float4 w1 = *(const float4*)(w + 4 * t + 1024);
    float4 b0 = *(const float4*)(b + 4 * t);
    float4 b1 = *(const float4*)(b + 4 * t + 1024);

    float o0x = (v0.x - mean) * r * w0.x + b0.x;
    float o0y = (v0.y - mean) * r * w0.y + b0.y;
    float o0z = (v0.z - mean) * r * w0.z + b0.z;
    float o0w = (v0.w - mean) * r * w0.w + b0.w;
    float o1x = (v1.x - mean) * r * w1.x + b1.x;
    float o1y = (v1.y - mean) * r * w1.y + b1.y;
    float o1z = (v1.z - mean) * r * w1.z + b1.z;
    float o1w = (v1.w - mean) * r * w1.w + b1.w;

    split2_store(o0x, o0y, oh, ol, base + 4 * t);
    split2_store(o0z, o0w, oh, ol, base + 4 * t + 2);
    split2_store(o1x, o1y, oh, ol, base + 4 * t + 1024);
    split2_store(o1z, o1w, oh, ol, base + 4 * t + 1026);
}

// ---------------------------------------------------------------------------
// HMMA GEMM (unchanged engine from R8) + new EPI_SPLIT epilogue
// ---------------------------------------------------------------------------
#define EPI_QKV   0   // fp32 out = acc + bias
#define EPI_GELU  1   // bf16 hi/lo out = split(gelu(acc + bias))
#define EPI_RES   2   // fp32 out = acc + bias + res
#define EPI_SPLIT 3   // bf16 hi/lo out = split(acc + bias)

#define BM 128
#define BN 128
#define BK 32
#define ROWB 80
#define SA_H 0
#define SA_L 10240
#define SB_H 20480
#define SB_L 30720
#define STAGE_BYTES 40960
#define HMMA_SMEM (3 * STAGE_BYTES)

__device__ __forceinline__ float gelu_tanh(float x) {
    float x3 = x * x * x;
    float t = tanhf(0.7978845608028654f * (x + 0.044715f * x3));
    return 0.5f * x * (1.f + t);
}

__device__ __forceinline__ void g2s_stage(
    uint32_t sb, const __nv_bfloat16* __restrict__ Ah, const __nv_bfloat16* __restrict__ Al,
    const __nv_bfloat16* __restrict__ Bh, const __nv_bfloat16* __restrict__ Bl,
    int bm, int bn, int K, int k0, int tid)
{
#pragma unroll
    for (int it = 0; it < 2; it++) {
        int c = tid + it * 256;
        int row = c >> 2, ch = c & 3;
        uint32_t off = (uint32_t)row * ROWB + ch * 16;
        size_t ga = (size_t)(bm + row) * K + k0 + ch * 8;
        size_t gb = (size_t)(bn + row) * K + k0 + ch * 8;
        cpa16(sb + SA_H + off, Ah + ga);
        cpa16(sb + SA_L + off, Al + ga);
        cpa16(sb + SB_H + off, Bh + gb);
        cpa16(sb + SB_L + off, Bl + gb);
    }
    CP_COMMIT();
}

template <int EPI>
__global__ __launch_bounds__(256, 1) void hmma_kernel(
    const __nv_bfloat16* __restrict__ Ah, const __nv_bfloat16* __restrict__ Al,
    const __nv_bfloat16* __restrict__ Bh, const __nv_bfloat16* __restrict__ Bl,
    const float* __restrict__ bias, const float* __restrict__ res,
    float* __restrict__ Cf, __nv_bfloat16* __restrict__ Chi,
    __nv_bfloat16* __restrict__ Clo, int M, int N, int K)
{
    extern __shared__ char smem[];
    uint32_t sb0 = smem_to_u32(smem);
    int tid = threadIdx.x;
    int wid = tid >> 5, lane = tid & 31;
    int wm = (wid & 1) * 64, wn = (wid >> 1) * 32;
    int bm = blockIdx.y * BM, bn = blockIdx.x * BN;

    float acc[4][4][4];
#pragma unroll
    for (int i = 0; i < 4; i++)
#pragma unroll
        for (int j = 0; j < 4; j++)
#pragma unroll
            for (int k = 0; k < 4; k++) acc[i][j][k] = 0.f;

    uint32_t a_off = (uint32_t)(wm + (lane & 15)) * ROWB + ((lane >> 4) * 16);
    uint32_t b_off = (uint32_t)(wn + (lane & 7) + ((lane >> 4) * 8)) * ROWB
                   + (((lane >> 3) & 1) * 16);

    g2s_stage(sb0,               Ah, Al, Bh, Bl, bm, bn, K, 0,  tid);
    g2s_stage(sb0 + STAGE_BYTES, Ah, Al, Bh, Bl, bm, bn, K, BK, tid);

    int nk = K / BK;
    for (int kt = 0; kt < nk; kt++) {
        asm volatile("cp.async.wait_group 1;" ::: "memory");
        __syncthreads();
        if (kt + 2 < nk)
            g2s_stage(sb0 + (uint32_t)((kt + 2) % 3) * STAGE_BYTES,
                      Ah, Al, Bh, Bl, bm, bn, K, (kt + 2) * BK, tid);
        else
            CP_COMMIT();

        uint32_t st = sb0 + (uint32_t)(kt % 3) * STAGE_BYTES;
#pragma unroll
        for (int ks = 0; ks < 2; ks++) {
            uint32_t koff = (uint32_t)ks * 32;
            uint32_t ah[4][4], al[4][4];
#pragma unroll
            for (int mi = 0; mi < 4; mi++) {
                uint32_t ra = st + SA_H + a_off + (uint32_t)mi * (16 * ROWB) + koff;
                ldsm4(ah[mi][0], ah[mi][1], ah[mi][2], ah[mi][3], ra);
                ldsm4(al[mi][0], al[mi][1], al[mi][2], al[mi][3], ra + (SA_L - SA_H));
            }
            uint32_t bh[2][4], bl[2][4];
#pragma unroll
            for (int ng = 0; ng < 2; ng++) {
                uint32_t rb = st + SB_H + b_off + (uint32_t)ng * (16 * ROWB) + koff;
                ldsm4(bh[ng][0], bh[ng][1], bh[ng][2], bh[ng][3], rb);
                ldsm4(bl[ng][0], bl[ng][1], bl[ng][2], bl[ng][3], rb + (SB_L - SB_H));
            }
#pragma unroll
            for (int mi = 0; mi < 4; mi++)
#pragma unroll
                for (int nf = 0; nf < 4; nf++) {
                    const uint32_t* B0 = &bh[nf >> 1][(nf & 1) * 2];
                    const uint32_t* B1 = &bl[nf >> 1][(nf & 1) * 2];
                    mma16816(acc[mi][nf], ah[mi], B0);
                    mma16816(acc[mi][nf], ah[mi], B1);
                    mma16816(acc[mi][nf], al[mi], B0);
                }
        }
    }

    int mrow = bm + wm + (lane >> 2);
    int ncol0 = (lane & 3) * 2;
#pragma unroll
    for (int mi = 0; mi < 4; mi++) {
        int m0 = mrow + mi * 16;
#pragma unroll
        for (int nf = 0; nf < 4; nf++) {
            int n0 = bn + wn + nf * 8 + ncol0;
            float b0 = bias[n0], b1 = bias[n0 + 1];
            float v00 = acc[mi][nf][0] + b0, v01 = acc[mi][nf][1] + b1;
            float v10 = acc[mi][nf][2] + b0, v11 = acc[mi][nf][3] + b1;
            size_t o0 = (size_t)m0 * N + n0;
            size_t o1 = (size_t)(m0 + 8) * N + n0;
            if (EPI == EPI_GELU) {
                split2_store(gelu_tanh(v00), gelu_tanh(v01), Chi, Clo, o0);
                split2_store(gelu_tanh(v10), gelu_tanh(v11), Chi, Clo, o1);
            } else if (EPI == EPI_SPLIT) {
                split2_store(v00, v01, Chi, Clo, o0);
                split2_store(v10, v11, Chi, Clo, o1);
            } else {
                if (EPI == EPI_RES) {
                    float2 r0 = *(const float2*)(res + o0);
                    float2 r1 = *(const float2*)(res + o1);
                    v00 += r0.x; v01 += r0.y; v10 += r1.x; v11 += r1.y;
                }
                float2 s0 = {v00, v01}, s1 = {v10, v11};
                *(float2*)(Cf + o0) = s0;
                *(float2*)(Cf + o1) = s1;
            }
        }
    }
}

// ---------------------------------------------------------------------------
// Flash attention on mma.sync (bf16 split, causal).
// CTA: 128 q rows, 8 warps (warp w owns rows w*16..w*16+15). kv tiles of 64.
// Q hi/lo parked in smem; K/V hi/lo double-buffered cp.async.
// ---------------------------------------------------------------------------
#define AROW 272                       // 128 bf16 + 8 pad = 272 bytes/row
#define AT_KH 0
#define AT_KL 17408
#define AT_VH 34816
#define AT_VL 52224
#define AT_STAGE 69632
#define AT_QH (2 * AT_STAGE)           // 139264
#define AT_QL (AT_QH + 128 * AROW)     // 174080
#define ATTN_SMEM (AT_QL + 128 * AROW) // 208896

__device__ __forceinline__ void attn_load_kv(
    uint32_t st, const __nv_bfloat16* __restrict__ qh, const __nv_bfloat16* __restrict__ ql,
    int bb, int h, int k0, int tid)
{
#pragma unroll
    for (int it = 0; it < 4; it++) {
        int c = tid + it * 256;
        int row = c >> 4, ch = c & 15;
        uint32_t off = (uint32_t)row * AROW + ch * 16;
        size_t g = (size_t)(bb * S_ + k0 + row) * QKV_STRIDE + h * D_ + ch * 8;
        cpa16(st + AT_KH + off, qh + g + E_);
        cpa16(st + AT_KL + off, ql + g + E_);
        cpa16(st + AT_VH + off, qh + g + 2 * E_);
        cpa16(st + AT_VL + off, ql + g + 2 * E_);
    }
    CP_COMMIT();
}

__global__ __launch_bounds__(256, 1) void attn_mma_kernel(
    const __nv_bfloat16* __restrict__ qkvh, const __nv_bfloat16* __restrict__ qkvl,
    __nv_bfloat16* __restrict__ ctx_hi, __nv_bfloat16* __restrict__ ctx_lo)
{
    extern __shared__ char smem[];
    uint32_t sb = smem_to_u32(smem);
    int tid = threadIdx.x;
    int wid = tid >> 5, lane = tid & 31;
    int q0 = blockIdx.x * 128;
    int h = blockIdx.y, bb = blockIdx.z;
    int wbase = wid * 16;

    // ---- load Q tile (128 x 128) hi/lo into permanent smem region ----
#pragma unroll
    for (int it = 0; it < 8; it++) {
        int c = tid + it * 256;
        int row = c >> 4, ch = c & 15;
        uint32_t off = (uint32_t)row * AROW + ch * 16;
        size_t g = (size_t)(bb * S_ + q0 + row) * QKV_STRIDE + h * D_ + ch * 8;
        cpa16(sb + AT_QH + off, qkvh + g);
        cpa16(sb + AT_QL + off, qkvl + g);
    }
    CP_COMMIT();                           // group: Q
    attn_load_kv(sb, qkvh, qkvl, bb, h, 0, tid);   // group: tile 0

    // fragment address components
    uint32_t a_off = (uint32_t)(wbase + (lane & 15)) * AROW + ((lane >> 4) * 16);
    uint32_t b_off = (uint32_t)((lane & 7) + ((lane >> 4) * 8)) * AROW + (((lane >> 3) & 1) * 16);
    uint32_t v_off = (uint32_t)(lane & 15) * AROW + ((lane >> 4) * 8) * 2;

    const float SCL = 0.08838834764831845f * 1.4426950408889634f; // rsqrt(D)*log2e
    int row_lo = q0 + wbase + (lane >> 2);
    int row_hi = row_lo + 8;

    float o[16][4];
#pragma unroll
    for (int i = 0; i < 16; i++)
#pragma unroll
        for (int j = 0; j < 4; j++) o[i][j] = 0.f;
    float m_lo = -1e30f, m_hi = -1e30f, l_lo = 0.f, l_hi = 0.f;

    int nt = q0 / 64 + 2;
    for (int t = 0; t < nt; t++) {
        uint32_t st = sb + (uint32_t)(t & 1) * AT_STAGE;
        if (t + 1 < nt) {
            attn_load_kv(sb + (uint32_t)((t + 1) & 1) * AT_STAGE, qkvh, qkvl, bb, h,
                         (t + 1) * 64, tid);
            asm volatile("cp.async.wait_group 1;" ::: "memory");
        } else {
            asm volatile("cp.async.wait_group 0;" ::: "memory");
        }
        __syncthreads();

        int k0 = t * 64;
        bool skip = (k0 > q0 + wbase + 15);
        if (!skip) {
            // ---- S = Q K^T (3-term split) ----
            float sacc[8][4];
#pragma unroll
            for (int i = 0; i < 8; i++)
#pragma unroll
                for (int j = 0; j < 4; j++) sacc[i][j] = 0.f;

#pragma unroll
            for (int ks = 0; ks < 8; ks++) {
                uint32_t koff = (uint32_t)ks * 32;
                uint32_t qfh[4], qfl[4];
                ldsm4(qfh[0], qfh[1], qfh[2], qfh[3], sb + AT_QH + a_off + koff);
                ldsm4(qfl[0], qfl[1], qfl[2], qfl[3], sb + AT_QL + a_off + koff);
#pragma unroll
                for (int g = 0; g < 4; g++) {
                    uint32_t kh[4], kl[4];
                    uint32_t rb = st + AT_KH + b_off + (uint32_t)g * (16 * AROW) + koff;
                    ldsm4(kh[0], kh[1], kh[2], kh[3], rb);
                    ldsm4(kl[0], kl[1], kl[2], kl[3], rb + (AT_KL - AT_KH));
                    mma16816(sacc[2 * g],     qfh, &kh[0]);
                    mma16816(sacc[2 * g],     qfh, &kl[0]);
                    mma16816(sacc[2 * g],     qfl, &kh[0]);
                    mma16816(sacc[2 * g + 1], qfh, &kh[2]);
                    mma16816(sacc[2 * g + 1], qfh, &kl[2]);
                    mma16816(sacc[2 * g + 1], qfl, &kh[2]);
                }
            }

            // ---- scale + causal mask (scores now in log2 units) ----
            bool needmask = (k0 + 63) > (q0 + wbase);
#pragma unroll
            for (int nf = 0; nf < 8; nf++) {
                int col = k0 + nf * 8 + (lane & 3) * 2;
                float s0 = sacc[nf][0] * SCL, s1 = sacc[nf][1] * SCL;
                float s2 = sacc[nf][2] * SCL, s3 = sacc[nf][3] * SCL;
                if (needmask) {
                    if (col     > row_lo) s0 = -1e30f;
                    if (col + 1 > row_lo) s1 = -1e30f;
                    if (col     > row_hi) s2 = -1e30f;
                    if (col + 1 > row_hi) s3 = -1e30f;
                }
                sacc[nf][0] = s0; sacc[nf][1] = s1; sacc[nf][2] = s2; sacc[nf][3] = s3;
            }

            // ---- online softmax ----
            float mx_lo = -1e30f, mx_hi = -1e30f;
#pragma unroll
            for (int nf = 0; nf < 8; nf++) {
                mx_lo = fmaxf(mx_lo, fmaxf(sacc[nf][0], sacc[nf][1]));
                mx_hi = fmaxf(mx_hi, fmaxf(sacc[nf][2], sacc[nf][3]));
            }
            mx_lo = fmaxf(mx_lo, __shfl_xor_sync(0xffffffffu, mx_lo, 1));
            mx_lo = fmaxf(mx_lo, __shfl_xor_sync(0xffffffffu, mx_lo, 2));
            mx_hi = fmaxf(mx_hi, __shfl_xor_sync(0xffffffffu, mx_hi, 1));
            mx_hi = fmaxf(mx_hi, __shfl_xor_sync(0xffffffffu, mx_hi, 2));

            float mn_lo = fmaxf(m_lo, mx_lo), mn_hi = fmaxf(m_hi, mx_hi);
            float al_lo = exp2f(m_lo - mn_lo), al_hi = exp2f(m_hi - mn_hi);
            m_lo = mn_lo; m_hi = mn_hi;

            float sum_lo = 0.f, sum_hi = 0.f;
#pragma unroll
            for (int nf = 0; nf < 8; nf++) {
                float p0 = exp2f(sacc[nf][0] - m_lo);
                float p1 = exp2f(sacc[nf][1] - m_lo);
                float p2 = exp2f(sacc[nf][2] - m_hi);
                float p3 = exp2f(sacc[nf][3] - m_hi);
                sum_lo += p0 + p1; sum_hi += p2 + p3;
                sacc[nf][0] = p0; sacc[nf][1] = p1; sacc[nf][2] = p2; sacc[nf][3] = p3;
            }
            sum_lo += __shfl_xor_sync(0xffffffffu, sum_lo, 1);
            sum_lo += __shfl_xor_sync(0xffffffffu, sum_lo, 2);
            sum_hi += __shfl_xor_sync(0xffffffffu, sum_hi, 1);
            sum_hi += __shfl_xor_sync(0xffffffffu, sum_hi, 2);
            l_lo = l_lo * al_lo + sum_lo;
            l_hi = l_hi * al_hi + sum_hi;

#pragma unroll
            for (int i = 0; i < 16; i++) {
                o[i][0] *= al_lo; o[i][1] *= al_lo;
                o[i][2] *= al_hi; o[i][3] *= al_hi;
            }

            // ---- pack P into A-fragments (hi/lo) ----
            uint32_t pah[4][4], pal[4][4];
#pragma unroll
            for (int ks = 0; ks < 4; ks++) {
                splitpack(sacc[2 * ks][0],     sacc[2 * ks][1],     pah[ks][0], pal[ks][0]);
                splitpack(sacc[2 * ks][2],     sacc[2 * ks][3],     pah[ks][1], pal[ks][1]);
                splitpack(sacc[2 * ks + 1][0], sacc[2 * ks + 1][1], pah[ks][2], pal[ks][2]);
                splitpack(sacc[2 * ks + 1][2], sacc[2 * ks + 1][3], pah[ks][3], pal[ks][3]);
            }

            // ---- O += P V (3-term split), V via ldmatrix.trans ----
#pragma unroll
            for (int ks = 0; ks < 4; ks++) {
#pragma unroll
                for (int dg = 0; dg < 8; dg++) {
                    uint32_t vh[4], vl[4];
                    uint32_t rv = st + AT_VH + v_off + (uint32_t)ks * (16 * AROW) + dg * 32;
                    ldsm4t(vh[0], vh[1], vh[2], vh[3], rv);
                    ldsm4t(vl[0], vl[1], vl[2], vl[3], rv + (AT_VL - AT_VH));
                    mma16816(o[2 * dg],     pah[ks], &vh[0]);
                    mma16816(o[2 * dg],     pah[ks], &vl[0]);
                    mma16816(o[2 * dg],     pal[ks], &vh[0]);
                    mma16816(o[2 * dg + 1], pah[ks], &vh[2]);
                    mma16816(o[2 * dg + 1], pah[ks], &vl[2]);
                    mma16816(o[2 * dg + 1], pal[ks], &vh[2]);
                }
            }
        }
        __syncthreads();
    }

    // ---- normalize + write ctx hi/lo ----
    float li_lo = 1.f / l_lo, li_hi = 1.f / l_hi;
    size_t base_lo = (size_t)(bb * S_ + row_lo) * E_ + h * D_;
    size_t base_hi = (size_t)(bb * S_ + row_hi) * E_ + h * D_;
#pragma unroll
    for (int dgf = 0; dgf < 16; dgf++) {
        int col = dgf * 8 + (lane & 3) * 2;
        split2_store(o[dgf][0] * li_lo, o[dgf][1] * li_lo, ctx_hi, ctx_lo, base_lo + col);
        split2_store(o[dgf][2] * li_hi, o[dgf][3] * li_hi, ctx_hi, ctx_lo, base_hi + col);
    }
}

// ---------------------------------------------------------------------------
// Launch
// ---------------------------------------------------------------------------
extern "C" void kernel_launch(void* const* d_in, const int* in_sizes, int n_in,
                              void* d_out, int out_size)
{
    const float* x            = (const float*)d_in[0];
    const float* ln1_w        = (const float*)d_in[1];
    const float* ln1_b        = (const float*)d_in[2];
    const float* c_attn_w     = (const float*)d_in[3];
    const float* c_attn_b     = (const float*)d_in[4];
    const float* c_proj_w     = (const float*)d_in[5];
    const float* c_proj_b     = (const float*)d_in[6];
    const float* ln2_w        = (const float*)d_in[7];
    const float* ln2_b        = (const float*)d_in[8];
    const float* c_fc_w       = (const float*)d_in[9];
    const float* c_fc_b       = (const float*)d_in[10];
    const float* c_mlp_proj_w = (const float*)d_in[11];
    const float* c_mlp_proj_b = (const float*)d_in[12];
    float* out = (float*)d_out;

    void *p_wh, *p_wl, *p_ah, *p_al, *p_fh, *p_fl;
    cudaGetSymbolAddress(&p_wh, g_wt_hi);
    cudaGetSymbolAddress(&p_wl, g_wt_lo);
    cudaGetSymbolAddress(&p_ah, g_act_hi);
    cudaGetSymbolAddress(&p_al, g_act_lo);
    cudaGetSymbolAddress(&p_fh, g_fc_hi);
    cudaGetSymbolAddress(&p_fl, g_fc_lo);
    __nv_bfloat16* wh = (__nv_bfloat16*)p_wh;
    __nv_bfloat16* wl = (__nv_bfloat16*)p_wl;
    __nv_bfloat16* ah = (__nv_bfloat16*)p_ah;
    __nv_bfloat16* al = (__nv_bfloat16*)p_al;
    __nv_bfloat16* fh = (__nv_bfloat16*)p_fh;   // also qkv hi plane
    __nv_bfloat16* fl = (__nv_bfloat16*)p_fl;   // also qkv lo plane

    cudaFuncSetAttribute(attn_mma_kernel, cudaFuncAttributeMaxDynamicSharedMemorySize, ATTN_SMEM);
    cudaFuncSetAttribute(hmma_kernel<EPI_SPLIT>, cudaFuncAttributeMaxDynamicSharedMemorySize, HMMA_SMEM);
    cudaFuncSetAttribute(hmma_kernel<EPI_GELU>,  cudaFuncAttributeMaxDynamicSharedMemorySize, HMMA_SMEM);
    cudaFuncSetAttribute(hmma_kernel<EPI_RES>,   cudaFuncAttributeMaxDynamicSharedMemorySize, HMMA_SMEM);

    dim3 tb(32, 8);
    wsplit_t_kernel<<<dim3(6144 / 32, 2048 / 32), tb>>>(c_attn_w,     wh + WOFF_QKV,  wl + WOFF_QKV,  2048, 6144);
    wsplit_t_kernel<<<dim3(2048 / 32, 2048 / 32), tb>>>(c_proj_w,     wh + WOFF_PROJ, wl + WOFF_PROJ, 2048, 2048);
    wsplit_t_kernel<<<dim3(8192 / 32, 2048 / 32), tb>>>(c_fc_w,       wh + WOFF_FC,   wl + WOFF_FC,   2048, 8192);
    wsplit_t_kernel<<<dim3(2048 / 32, 8192 / 32), tb>>>(c_mlp_proj_w, wh + WOFF_MLP,  wl + WOFF_MLP,  8192, 2048);

    // 1. ln1(x) -> act planes
    ln_kernel<<<NTOK, 256>>>(x, ln1_w, ln1_b, ah, al);

    // 2. qkv = ln1 @ Wqkv + b -> bf16 hi/lo planes (aliased into fc buffers)
    hmma_kernel<EPI_SPLIT><<<dim3(QKV_STRIDE / BN, NTOK / BM), 256, HMMA_SMEM>>>(
        ah, al, wh + WOFF_QKV, wl + WOFF_QKV, c_attn_b, nullptr,
        nullptr, fh, fl, NTOK, QKV_STRIDE, E_);

    // 3. attention (tensor-core) -> ctx planes
    attn_mma_kernel<<<dim3(S_ / 128, H_, B_), 256, ATTN_SMEM>>>(fh, fl, ah, al);

    // 4. x2 = ctx @ Wproj + b + x -> d_out (fp32)
    hmma_kernel<EPI_RES><<<dim3(E_ / BN, NTOK / BM), 256, HMMA_SMEM>>>(
        ah, al, wh + WOFF_PROJ, wl + WOFF_PROJ, c_proj_b, x,
        out, nullptr, nullptr, NTOK, E_, E_);

    // 5. ln2(x2) -> act planes
    ln_kernel<<<NTOK, 256>>>(out, ln2_w, ln2_b, ah, al);

    // 6. fc = gelu(ln2 @ Wfc + b) -> fc planes (overwrites qkv planes; safe)
    hmma_kernel<EPI_GELU><<<dim3(F_ / BN, NTOK / BM), 256, HMMA_SMEM>>>(
        ah, al, wh + WOFF_FC, wl + WOFF_FC, c_fc_b, nullptr,
        nullptr, fh, fl, NTOK, F_, E_);

    // 7. out = fc @ Wmlp + b + x2 -> d_out (fp32, in-place residual)
    hmma_kernel<EPI_RES><<<dim3(E_ / BN, NTOK / BM), 256, HMMA_SMEM>>>(
        fh, fl, wh + WOFF_MLP, wl + WOFF_MLP, c_mlp_proj_b, out,
        out, nullptr, nullptr, NTOK, E_, F_);

    (void)in_sizes; (void)n_in; (void)out_size;
}